// round 3
// baseline (speedup 1.0000x reference)
#include <cuda_runtime.h>
#include <math.h>

// Problem constants
#define BB   4
#define TT   2048
#define CC   2048
#define HH   16
#define DH   128
#define BT   (BB * TT)          // 8192
#define ELEMS ((size_t)BT * CC) // 16777216

// ---------------- scratch (device globals; no allocation allowed) ----------
__device__ __align__(16) float g_x[ELEMS];   // rmsnormed input
__device__ __align__(16) float g_q[ELEMS];
__device__ __align__(16) float g_k[ELEMS];
__device__ __align__(16) float g_v[ELEMS];
__device__ __align__(16) float g_y[ELEMS];   // attention output (pre-proj)
__device__ __align__(16) float g_cos[TT * 64];
__device__ __align__(16) float g_sin[TT * 64];

#define RMS_EPS 1.1920928955078125e-07f

// ---------------- kernel 1: rmsnorm over C of residual ---------------------
__global__ __launch_bounds__(256) void rmsnorm_in_kernel(const float* __restrict__ in,
                                                         float* __restrict__ out) {
    int row = blockIdx.x;
    const float4* ip = reinterpret_cast<const float4*>(in) + (size_t)row * 512;
    float4*       op = reinterpret_cast<float4*>(out)      + (size_t)row * 512;
    int t = threadIdx.x;
    float4 a = ip[t];
    float4 b = ip[t + 256];
    float ss = a.x*a.x + a.y*a.y + a.z*a.z + a.w*a.w
             + b.x*b.x + b.y*b.y + b.z*b.z + b.w*b.w;
    __shared__ float red[8];
    #pragma unroll
    for (int o = 16; o > 0; o >>= 1) ss += __shfl_xor_sync(0xffffffffu, ss, o);
    if ((t & 31) == 0) red[t >> 5] = ss;
    __syncthreads();
    if (t < 8) {
        float v = red[t];
        #pragma unroll
        for (int o = 4; o > 0; o >>= 1) v += __shfl_xor_sync(0xffu, v, o);
        if (t == 0) red[0] = v;
    }
    __syncthreads();
    float sc = rsqrtf(red[0] * (1.0f / 2048.0f) + RMS_EPS);
    a.x *= sc; a.y *= sc; a.z *= sc; a.w *= sc;
    b.x *= sc; b.y *= sc; b.z *= sc; b.w *= sc;
    op[t]       = a;
    op[t + 256] = b;
}

// ---------------- kernel 2: RoPE cos/sin tables (accurate inv_freq) --------
__global__ void rope_table_kernel() {
    int idx = blockIdx.x * blockDim.x + threadIdx.x;
    if (idx >= TT * 64) return;
    int t = idx >> 6;
    int p = idx & 63;
    double inv = pow(10000.0, -((double)p) / 64.0);   // exact-to-0.5ulp inv_freq
    float ang = (float)t * (float)inv;                // match ref fp32 product
    g_cos[idx] = cosf(ang);
    g_sin[idx] = sinf(ang);
}

// ---------------- kernel 3: SGEMM  C[m,n] = sum_k A[m,k]*W[n,k] (+addend) --
#define GBM 128
#define GBN 64
#define GBK 16

__global__ __launch_bounds__(256) void sgemm_nt_kernel(const float* __restrict__ A,
                                                       const float* __restrict__ W,
                                                       const float* __restrict__ addend,
                                                       float* __restrict__ Cmat,
                                                       int M, int N, int K) {
    __shared__ float As[GBK][132];   // transposed A tile [k][m], padded
    __shared__ float Bs[GBK][68];    // transposed W tile [k][n], padded
    int tid = threadIdx.x;
    int tx = tid & 15, ty = tid >> 4;
    int m0 = blockIdx.y * GBM, n0 = blockIdx.x * GBN;

    float acc[8][4];
    #pragma unroll
    for (int i = 0; i < 8; i++)
        #pragma unroll
        for (int j = 0; j < 4; j++) acc[i][j] = 0.f;

    for (int k0 = 0; k0 < K; k0 += GBK) {
        #pragma unroll
        for (int it = 0; it < 2; it++) {
            int f4i = tid + it * 256;         // 0..511
            int r = f4i >> 2, c4 = f4i & 3;
            float4 v = *reinterpret_cast<const float4*>(A + (size_t)(m0 + r) * K + k0 + 4 * c4);
            As[4*c4+0][r] = v.x; As[4*c4+1][r] = v.y;
            As[4*c4+2][r] = v.z; As[4*c4+3][r] = v.w;
        }
        {
            int r = tid >> 2, c4 = tid & 3;   // 0..63
            float4 v = *reinterpret_cast<const float4*>(W + (size_t)(n0 + r) * K + k0 + 4 * c4);
            Bs[4*c4+0][r] = v.x; Bs[4*c4+1][r] = v.y;
            Bs[4*c4+2][r] = v.z; Bs[4*c4+3][r] = v.w;
        }
        __syncthreads();
        #pragma unroll
        for (int kk = 0; kk < GBK; kk++) {
            float4 a0 = *reinterpret_cast<const float4*>(&As[kk][8 * ty]);
            float4 a1 = *reinterpret_cast<const float4*>(&As[kk][8 * ty + 4]);
            float4 b  = *reinterpret_cast<const float4*>(&Bs[kk][4 * tx]);
            float av[8] = {a0.x, a0.y, a0.z, a0.w, a1.x, a1.y, a1.z, a1.w};
            float bv[4] = {b.x, b.y, b.z, b.w};
            #pragma unroll
            for (int i = 0; i < 8; i++)
                #pragma unroll
                for (int j = 0; j < 4; j++)
                    acc[i][j] += av[i] * bv[j];
        }
        __syncthreads();
    }

    #pragma unroll
    for (int i = 0; i < 8; i++) {
        size_t idx = (size_t)(m0 + 8 * ty + i) * N + n0 + 4 * tx;
        float4 r = make_float4(acc[i][0], acc[i][1], acc[i][2], acc[i][3]);
        if (addend) {
            float4 ad = *reinterpret_cast<const float4*>(addend + idx);
            r.x += ad.x; r.y += ad.y; r.z += ad.z; r.w += ad.w;
        }
        *reinterpret_cast<float4*>(Cmat + idx) = r;
    }
}

// ---------------- kernel 4: per-head rmsnorm + RoPE (q and k, in place) ----
__global__ __launch_bounds__(256) void qknorm_rope_kernel(float* __restrict__ q,
                                                          float* __restrict__ k) {
    int gwarp = (blockIdx.x * 256 + threadIdx.x) >> 5;   // [0, BT*HH)
    int lane  = threadIdx.x & 31;
    int m = gwarp >> 4;         // b*T + t
    int h = gwarp & 15;
    int t = m & (TT - 1);
    size_t base = (size_t)m * CC + h * DH;

    float c0 = g_cos[t * 64 + lane],      s0 = g_sin[t * 64 + lane];
    float c1 = g_cos[t * 64 + 32 + lane], s1 = g_sin[t * 64 + 32 + lane];

    float* bufs[2] = {q, k};
    #pragma unroll
    for (int w = 0; w < 2; w++) {
        float* p = bufs[w] + base;
        float v0 = p[lane], v1 = p[lane + 32], v2 = p[lane + 64], v3 = p[lane + 96];
        float ss = v0*v0 + v1*v1 + v2*v2 + v3*v3;
        #pragma unroll
        for (int o = 16; o > 0; o >>= 1) ss += __shfl_xor_sync(0xffffffffu, ss, o);
        float sc = rsqrtf(ss * (1.0f / 128.0f) + RMS_EPS);
        v0 *= sc; v1 *= sc; v2 *= sc; v3 *= sc;
        // pair (d, d+64): y1 = x1*c + x2*s ; y2 = -x1*s + x2*c
        p[lane]      = v0 * c0 + v2 * s0;
        p[lane + 64] = v2 * c0 - v0 * s0;
        p[lane + 32] = v1 * c1 + v3 * s1;
        p[lane + 96] = v3 * c1 - v1 * s1;
    }
}

// ---------------- kernel 5: causal flash attention (fp32) ------------------
#define AT_BM 64
#define AT_BN 64
// smem layout (floats): Qst[128][68], Kst[128][68], Vs[64][128], Ps[64][68]
#define ATT_SMEM_FLOATS (2 * 128 * 68 + 64 * 128 + 64 * 68)
#define ATT_SMEM_BYTES  (ATT_SMEM_FLOATS * 4)

__global__ __launch_bounds__(256) void attn_kernel(const float* __restrict__ Q,
                                                   const float* __restrict__ K,
                                                   const float* __restrict__ V,
                                                   float* __restrict__ O) {
    extern __shared__ float sm[];
    float* Qst = sm;
    float* Kst = sm + 128 * 68;
    float* Vs  = sm + 2 * 128 * 68;
    float* Ps  = sm + 2 * 128 * 68 + 64 * 128;

    int tid = threadIdx.x;
    int tx = tid & 15, ty = tid >> 4;
    int qt = blockIdx.x;               // q tile
    int bh = blockIdx.y;
    int b = bh >> 4, h = bh & 15;
    int m0 = qt * AT_BM;
    size_t base = (size_t)b * TT * CC + (size_t)h * DH;
    const float qscale = 1.0f / sqrtf((float)DH);

    // load Q tile transposed + prescaled
    for (int idx = tid; idx < AT_BM * 128; idx += 256) {
        int d = idx & 127, r = idx >> 7;
        Qst[d * 68 + r] = Q[base + (size_t)(m0 + r) * CC + d] * qscale;
    }

    float o[4][8];
    float mrun[4], lrun[4];
    #pragma unroll
    for (int i = 0; i < 4; i++) {
        mrun[i] = -1e30f; lrun[i] = 0.f;
        #pragma unroll
        for (int j = 0; j < 8; j++) o[i][j] = 0.f;
    }

    for (int kt = 0; kt <= qt; kt++) {
        int n0 = kt * AT_BN;
        __syncthreads();   // prior-iteration smem reads done; also publishes Q load

        // K tile transposed [d][n]
        for (int idx = tid; idx < AT_BN * 128; idx += 256) {
            int d = idx & 127, n = idx >> 7;
            Kst[d * 68 + n] = K[base + (size_t)(n0 + n) * CC + d];
        }
        // V tile plain [n][d]
        for (int f = tid; f < AT_BN * 32; f += 256) {
            int n = f >> 5, d4 = f & 31;
            reinterpret_cast<float4*>(Vs)[n * 32 + d4] =
                *reinterpret_cast<const float4*>(V + base + (size_t)(n0 + n) * CC + 4 * d4);
        }
        __syncthreads();

        // S = Q K^T fragment (rows 4ty+i, cols 4tx+j)
        float s[4][4];
        #pragma unroll
        for (int i = 0; i < 4; i++)
            #pragma unroll
            for (int j = 0; j < 4; j++) s[i][j] = 0.f;
        for (int d = 0; d < 128; d++) {
            float4 a  = *reinterpret_cast<const float4*>(&Qst[d * 68 + 4 * ty]);
            float4 bb = *reinterpret_cast<const float4*>(&Kst[d * 68 + 4 * tx]);
            float av[4] = {a.x, a.y, a.z, a.w};
            float bv[4] = {bb.x, bb.y, bb.z, bb.w};
            #pragma unroll
            for (int i = 0; i < 4; i++)
                #pragma unroll
                for (int j = 0; j < 4; j++)
                    s[i][j] += av[i] * bv[j];
        }

        bool diag = (kt == qt);
        #pragma unroll
        for (int i = 0; i < 4; i++) {
            int rg = m0 + 4 * ty + i;
            float mloc = -1e30f;
            #pragma unroll
            for (int j = 0; j < 4; j++) {
                if (diag && (n0 + 4 * tx + j > rg)) s[i][j] = -1e30f;
                mloc = fmaxf(mloc, s[i][j]);
            }
            #pragma unroll
            for (int off = 8; off > 0; off >>= 1)
                mloc = fmaxf(mloc, __shfl_xor_sync(0xffffffffu, mloc, off));
            float mnew  = fmaxf(mrun[i], mloc);
            float alpha = expf(mrun[i] - mnew);
            float rs = 0.f;
            #pragma unroll
            for (int j = 0; j < 4; j++) { s[i][j] = expf(s[i][j] - mnew); rs += s[i][j]; }
            #pragma unroll
            for (int off = 8; off > 0; off >>= 1)
                rs += __shfl_xor_sync(0xffffffffu, rs, off);
            lrun[i] = lrun[i] * alpha + rs;
            mrun[i] = mnew;
            #pragma unroll
            for (int j = 0; j < 8; j++) o[i][j] *= alpha;
            #pragma unroll
            for (int j = 0; j < 4; j++)
                Ps[(4 * ty + i) * 68 + 4 * tx + j] = s[i][j];
        }
        __syncthreads();

        // O += P V   (rows 4ty+i, cols 8tx+j)
        for (int n = 0; n < AT_BN; n++) {
            float pp[4];
            #pragma unroll
            for (int i = 0; i < 4; i++) pp[i] = Ps[(4 * ty + i) * 68 + n];
            float4 v0 = *reinterpret_cast<const float4*>(&Vs[n * 128 + 8 * tx]);
            float4 v1 = *reinterpret_cast<const float4*>(&Vs[n * 128 + 8 * tx + 4]);
            float vv[8] = {v0.x, v0.y, v0.z, v0.w, v1.x, v1.y, v1.z, v1.w};
            #pragma unroll
            for (int i = 0; i < 4; i++)
                #pragma unroll
                for (int j = 0; j < 8; j++)
                    o[i][j] += pp[i] * vv[j];
        }
    }

    // write normalized O into [b,t,h,d] (= [m][h*128+d]) layout
    #pragma unroll
    for (int i = 0; i < 4; i++) {
        float inv = 1.0f / lrun[i];
        size_t oidx = base + (size_t)(m0 + 4 * ty + i) * CC + 8 * tx;
        float4 r0 = make_float4(o[i][0] * inv, o[i][1] * inv, o[i][2] * inv, o[i][3] * inv);
        float4 r1 = make_float4(o[i][4] * inv, o[i][5] * inv, o[i][6] * inv, o[i][7] * inv);
        *reinterpret_cast<float4*>(O + oidx)     = r0;
        *reinterpret_cast<float4*>(O + oidx + 4) = r1;
    }
}

// ---------------- launch ----------------------------------------------------
extern "C" void kernel_launch(void* const* d_in, const int* in_sizes, int n_in,
                              void* d_out, int out_size) {
    const float* residual = (const float*)d_in[0];
    const float* wq    = (const float*)d_in[1];
    const float* wk    = (const float*)d_in[2];
    const float* wv    = (const float*)d_in[3];
    const float* wproj = (const float*)d_in[4];
    float* out = (float*)d_out;

    cudaFuncSetAttribute(attn_kernel, cudaFuncAttributeMaxDynamicSharedMemorySize,
                         ATT_SMEM_BYTES);

    void *px, *pq, *pk, *pv, *py;
    cudaGetSymbolAddress(&px, g_x);
    cudaGetSymbolAddress(&pq, g_q);
    cudaGetSymbolAddress(&pk, g_k);
    cudaGetSymbolAddress(&pv, g_v);
    cudaGetSymbolAddress(&py, g_y);
    float* gx = (float*)px; float* gq = (float*)pq; float* gk = (float*)pk;
    float* gv = (float*)pv; float* gy = (float*)py;

    // 1. rmsnorm input
    rmsnorm_in_kernel<<<BT, 256>>>(residual, gx);
    // 2. rope tables (deterministic, rebuilt each replay)
    rope_table_kernel<<<(TT * 64 + 255) / 256, 256>>>();
    // 3. QKV projections
    dim3 ggrid(CC / GBN, BT / GBM);
    sgemm_nt_kernel<<<ggrid, 256>>>(gx, wq, nullptr, gq, BT, CC, CC);
    sgemm_nt_kernel<<<ggrid, 256>>>(gx, wk, nullptr, gk, BT, CC, CC);
    sgemm_nt_kernel<<<ggrid, 256>>>(gx, wv, nullptr, gv, BT, CC, CC);
    // 4. per-head rmsnorm + rope on q, k
    qknorm_rope_kernel<<<(BT * HH) / 8, 256>>>(gq, gk);
    // 5. causal flash attention
    dim3 agrid(TT / AT_BM, BB * HH);
    attn_kernel<<<agrid, 256, ATT_SMEM_BYTES>>>(gq, gk, gv, gy);
    // 6. output projection + residual add
    sgemm_nt_kernel<<<ggrid, 256>>>(gy, wproj, residual, out, BT, CC, CC);
}